// round 17
// baseline (speedup 1.0000x reference)
#include <cuda_runtime.h>
#include <math.h>

#define BB   4
#define NPTS 4096
#define KNN  16
#define CIN  61
#define INF  64
#define OUTF 128
#define NROW (BB*NPTS)          // 16384
#define NITEM (NROW*KNN)        // 262144
#define HALFITEM (NITEM/2)      // 131072

typedef unsigned long long u64;
typedef unsigned int       u32;

// ------------------- device scratch (no allocations allowed) ----------------
__device__ int   g_idx[NITEM];
__device__ float g_feat1[NROW*INF];
__device__ float g_lin1[NROW*OUTF];
__device__ float g_lin2[NROW*OUTF];
__device__ float g_part[2*512*256];
__device__ float g_bn[2*2*OUTF];

// ---------- MLP weights in constant memory (separate cache port) ------------
__constant__ __align__(16) float cw1[10*32];
__constant__ __align__(16) float cb1[32];
__constant__ __align__(16) float cw2[32*64];
__constant__ __align__(16) float cb2[64];
__constant__ __align__(16) float cw3[64*64];
__constant__ __align__(16) float cb3[64];

// ---------------- packed fp32x2 helpers (FFMA2 pipe) ------------------------
__device__ __forceinline__ u64 pk2(float a) {
    u64 r; asm("mov.b64 %0,{%1,%1};" : "=l"(r) : "f"(a)); return r;
}
__device__ __forceinline__ u64 pk(float lo, float hi) {
    u64 r; asm("mov.b64 %0,{%1,%2};" : "=l"(r) : "f"(lo), "f"(hi)); return r;
}
__device__ __forceinline__ u64 fma2(u64 a, u64 b, u64 c) {
    u64 d; asm("fma.rn.f32x2 %0,%1,%2,%3;" : "=l"(d) : "l"(a), "l"(b), "l"(c)); return d;
}
__device__ __forceinline__ float2 upk(u64 v) {
    float2 f; asm("mov.b64 {%0,%1},%2;" : "=f"(f.x), "=f"(f.y) : "l"(v)); return f;
}

// ----------------------- profiling alignment nop ----------------------------
__global__ void nop_kernel() {}

// ===== K1: exact KNN v7 — radix histogram, register candidates, full occ ====
__global__ __launch_bounds__(512, 2) void knn_kernel(const float* __restrict__ pos) {
    extern __shared__ float sm[];
    float* sp    = sm;                        // [NPTS*3]
    u32*   hist  = (u32*)(sm + NPTS*3);       // [2048]
    u32*   swarp = hist + 2048;               // [16]
    u32*   listv = swarp + 16;                // [512]
    int*   listj = (int*)(listv + 512);       // [512]
    int*   outj  = listj + 512;               // [16]
    int*   ctl   = outj + 16;                 // [4]

    const int tid  = threadIdx.x;
    const int lane = tid & 31;
    const int wid  = tid >> 5;
    const int b    = blockIdx.x >> 8;
    const int q0   = (blockIdx.x & 255) << 4;
    const float* pb = pos + (size_t)b * NPTS * 3;

    for (int i = tid; i < NPTS*3; i += 512) sp[i] = pb[i];
    __syncthreads();

    float px[8], py[8], pz[8];
#pragma unroll
    for (int t = 0; t < 8; t++) {
        const int j = tid + 512*t;
        px[t] = sp[3*j]; py[t] = sp[3*j+1]; pz[t] = sp[3*j+2];
    }

    for (int qi = 0; qi < 16; qi++) {
        const int q = q0 + qi;
        ((uint4*)hist)[tid] = make_uint4(0,0,0,0);
        if (tid == 0) { ctl[0] = 0; ctl[1] = 0; }
        __syncthreads();

        const float qx = sp[3*q], qy = sp[3*q+1], qz = sp[3*q+2];

        u32 kk[8];
#pragma unroll
        for (int t = 0; t < 8; t++) {
            const float dx = qx - px[t], dy = qy - py[t], dz = qz - pz[t];
            // match XLA rounding: no fma contraction, left-to-right sum
            kk[t] = __float_as_uint(__fadd_rn(__fadd_rn(__fmul_rn(dx,dx),
                        __fmul_rn(dy,dy)), __fmul_rn(dz,dz)));
            atomicAdd(&hist[kk[t] >> 21], 1u);
        }
        __syncthreads();

        u32 part;
        {
            const uint4 h4 = ((const uint4*)hist)[tid];
            part = (h4.x + h4.y) + (h4.z + h4.w);
        }
        u32 v = part;
#pragma unroll
        for (int off = 1; off < 32; off <<= 1) {
            u32 nb = __shfl_up_sync(0xffffffffu, v, off);
            if (lane >= off) v += nb;
        }
        if (lane == 31) swarp[wid] = v;
        __syncthreads();
        u32 base = 0;
#pragma unroll
        for (int w = 0; w < 16; w++) base += (w < wid) ? swarp[w] : 0u;
        const u32 incl = base + v, excl = incl - part;
        if (excl < 16u && incl >= 16u) {
            u32 c = excl;
#pragma unroll
            for (int k2 = 0; k2 < 4; k2++) {
                const u32 h = hist[tid*4 + k2];
                if (c < 16u && c + h >= 16u) { ctl[2] = tid*4 + k2; ctl[3] = (int)c; break; }
                c += h;
            }
        }
        __syncthreads();
        const u32 bstar = (u32)ctl[2];
        const int Lb    = ctl[3];

#pragma unroll
        for (int t = 0; t < 8; t++) {
            const u32 key = kk[t] >> 21;
            if (key < bstar) {
                const int p = atomicAdd(&ctl[0], 1);
                outj[p] = tid + 512*t;
            } else if (key == bstar) {
                const int p = atomicAdd(&ctl[1], 1);
                if (p < 512) { listv[p] = kk[t]; listj[p] = tid + 512*t; }
            }
        }
        __syncthreads();

        const int cnt = min(ctl[1], 512), need = 16 - Lb;
        if (tid < cnt) {
            const u64 me = ((u64)listv[tid] << 32) | (u32)listj[tid];
            int rank = 0;
            for (int i = 0; i < cnt; i++)
                rank += ((((u64)listv[i] << 32) | (u32)listj[i]) < me);
            if (rank < need) outj[Lb + rank] = listj[tid];
        }
        __syncthreads();
        if (tid < 16) g_idx[((b*NPTS + q) << 4) + tid] = outj[tid];
        __syncthreads();
    }
}

// == K2: per-neighbor MLP, 2 items/thread (const-port traffic amortized) =====
// Thread handles item (b, n, k) and (b+2, n, k): every weight LDC feeds both.
__global__ __launch_bounds__(128) void relconv_kernel(
    const float* __restrict__ x, const float* __restrict__ pos) {

    const int tid  = threadIdx.x;
    const int item = blockIdx.x * 128 + tid;       // 0..131071 (b in {0,1})
    const int k  = item & (KNN-1);
    const int n  = (item >> 4) & (NPTS-1);
    const int b0 = item >> 16;
    const int b1 = b0 + 2;
    const int j0 = g_idx[item];
    const int j1 = g_idx[item + HALFITEM];

    const float* pb0 = pos + (size_t)b0 * NPTS * 3;
    const float* pb1 = pos + (size_t)b1 * NPTS * 3;
    const float cx0 = pb0[3*n], cy0 = pb0[3*n+1], cz0 = pb0[3*n+2];
    const float gx0 = pb0[3*j0], gy0 = pb0[3*j0+1], gz0 = pb0[3*j0+2];
    const float cx1 = pb1[3*n], cy1 = pb1[3*n+1], cz1 = pb1[3*n+2];
    const float gx1 = pb1[3*j1], gy1 = pb1[3*j1+1], gz1 = pb1[3*j1+2];
    const float rx0 = gx0 - cx0, ry0 = gy0 - cy0, rz0 = gz0 - cz0;
    const float rx1 = gx1 - cx1, ry1 = gy1 - cy1, rz1 = gz1 - cz1;
    const float s20 = rx0*rx0 + ry0*ry0 + rz0*rz0;
    const float s21 = rx1*rx1 + ry1*ry1 + rz1*rz1;
    const float dis0 = (s20 > 0.f) ? sqrtf(s20) : 0.f;
    const float dis1 = (s21 > 0.f) ? sqrtf(s21) : 0.f;

    const float f0[10] = {cx0, cy0, cz0, gx0, gy0, gz0, rx0, ry0, rz0, dis0};
    const float f1[10] = {cx1, cy1, cz1, gx1, gy1, gz1, rx1, ry1, rz1, dis1};

    // layer1: 10 -> 32, relu (both items share each weight LDC)
    u64 a1p[16], b1p[16];
#pragma unroll
    for (int d = 0; d < 16; d++) { a1p[d] = ((const u64*)cb1)[d]; b1p[d] = a1p[d]; }
#pragma unroll
    for (int c = 0; c < 10; c++) {
        const u64 aa0 = pk2(f0[c]), aa1 = pk2(f1[c]);
        const ulonglong2* wrow = (const ulonglong2*)(cw1 + c*32);
#pragma unroll
        for (int dq = 0; dq < 8; dq++) {
            const ulonglong2 ww = wrow[dq];
            a1p[2*dq]   = fma2(aa0, ww.x, a1p[2*dq]);
            a1p[2*dq+1] = fma2(aa0, ww.y, a1p[2*dq+1]);
            b1p[2*dq]   = fma2(aa1, ww.x, b1p[2*dq]);
            b1p[2*dq+1] = fma2(aa1, ww.y, b1p[2*dq+1]);
        }
    }
    float h1a[32], h1b[32];
#pragma unroll
    for (int d = 0; d < 16; d++) {
        float2 t0 = upk(a1p[d]), t1 = upk(b1p[d]);
        h1a[2*d] = fmaxf(t0.x, 0.f); h1a[2*d+1] = fmaxf(t0.y, 0.f);
        h1b[2*d] = fmaxf(t1.x, 0.f); h1b[2*d+1] = fmaxf(t1.y, 0.f);
    }

    // layer2: 32 -> 64, relu — two halves of 16 u64 accumulators per item
    float h2a[64], h2b[64];
#pragma unroll
    for (int half = 0; half < 2; half++) {
        u64 acc0[16], acc1[16];
#pragma unroll
        for (int d = 0; d < 16; d++) {
            acc0[d] = ((const u64*)cb2)[half*16 + d]; acc1[d] = acc0[d];
        }
#pragma unroll
        for (int c = 0; c < 32; c++) {
            const u64 aa0 = pk2(h1a[c]), aa1 = pk2(h1b[c]);
            const ulonglong2* wrow = (const ulonglong2*)(cw2 + c*64 + half*32);
#pragma unroll
            for (int dq = 0; dq < 8; dq++) {
                const ulonglong2 ww = wrow[dq];
                acc0[2*dq]   = fma2(aa0, ww.x, acc0[2*dq]);
                acc0[2*dq+1] = fma2(aa0, ww.y, acc0[2*dq+1]);
                acc1[2*dq]   = fma2(aa1, ww.x, acc1[2*dq]);
                acc1[2*dq+1] = fma2(aa1, ww.y, acc1[2*dq+1]);
            }
        }
#pragma unroll
        for (int d = 0; d < 16; d++) {
            float2 t0 = upk(acc0[d]), t1 = upk(acc1[d]);
            h2a[half*32 + 2*d]     = fmaxf(t0.x, 0.f);
            h2a[half*32 + 2*d + 1] = fmaxf(t0.y, 0.f);
            h2b[half*32 + 2*d]     = fmaxf(t1.x, 0.f);
            h2b[half*32 + 2*d + 1] = fmaxf(t1.y, 0.f);
        }
    }

    // layer3: 64 -> 64 (no relu), 4 chunks of 8 u64/item; fused epilogue
    const float* xr0 = x + ((size_t)b0 * NPTS + j0) * CIN;
    const float* xr1 = x + ((size_t)b1 * NPTS + j1) * CIN;
    float* outp0 = g_feat1 + ((size_t)b0 * NPTS + n) * INF;
    float* outp1 = g_feat1 + ((size_t)b1 * NPTS + n) * INF;
#pragma unroll
    for (int q4 = 0; q4 < 4; q4++) {
        u64 acc0[8], acc1[8];
#pragma unroll
        for (int d = 0; d < 8; d++) {
            acc0[d] = ((const u64*)cb3)[q4*8 + d]; acc1[d] = acc0[d];
        }
#pragma unroll
        for (int c = 0; c < 64; c++) {
            const u64 aa0 = pk2(h2a[c]), aa1 = pk2(h2b[c]);
            const ulonglong2* wrow = (const ulonglong2*)(cw3 + c*64 + q4*16);
#pragma unroll
            for (int dq = 0; dq < 4; dq++) {
                const ulonglong2 ww = wrow[dq];
                acc0[2*dq]   = fma2(aa0, ww.x, acc0[2*dq]);
                acc0[2*dq+1] = fma2(aa0, ww.y, acc0[2*dq+1]);
                acc1[2*dq]   = fma2(aa1, ww.x, acc1[2*dq]);
                acc1[2*dq+1] = fma2(aa1, ww.y, acc1[2*dq+1]);
            }
        }
        // weights * feat, warp max over k (16 lanes), relu, store (k==0)
#pragma unroll
        for (int d = 0; d < 8; d++) {
            const float2 t0 = upk(acc0[d]);
            const float2 t1 = upk(acc1[d]);
            const int ch0 = q4*16 + 2*d, ch1 = ch0 + 1;
            float fa0, fa1, fb0, fb1;
            if (ch0 < CIN)       { fa0 = xr0[ch0]; fb0 = xr1[ch0]; }
            else if (ch0 == 62)  { fa0 = gy0;      fb0 = gy1; }
            else                 { fa0 = gx0;      fb0 = gx1; }
            if (ch1 < CIN)       { fa1 = xr0[ch1]; fb1 = xr1[ch1]; }
            else if (ch1 == 61)  { fa1 = gx0;      fb1 = gx1; }
            else                 { fa1 = gz0;      fb1 = gz1; }
            float v0 = t0.x * fa0;
            float v1 = t0.y * fa1;
            float w0 = t1.x * fb0;
            float w1 = t1.y * fb1;
#pragma unroll
            for (int off = 8; off >= 1; off >>= 1) {
                v0 = fmaxf(v0, __shfl_xor_sync(0xffffffffu, v0, off));
                v1 = fmaxf(v1, __shfl_xor_sync(0xffffffffu, v1, off));
                w0 = fmaxf(w0, __shfl_xor_sync(0xffffffffu, w0, off));
                w1 = fmaxf(w1, __shfl_xor_sync(0xffffffffu, w1, off));
            }
            if (k == 0) {
                outp0[ch0] = fmaxf(v0, 0.f);
                outp0[ch1] = fmaxf(v1, 0.f);
                outp1[ch0] = fmaxf(w0, 0.f);
                outp1[ch1] = fmaxf(w1, 0.f);
            }
        }
    }
}

// ======== K3: GEMM1 [16384,64]@[64,128] + fb1, fused col-stats ==============
__global__ __launch_bounds__(256) void gemm1_kernel(
    const float* __restrict__ fw1, const float* __restrict__ fb1) {
    extern __shared__ float dyn[];
    float* sW    = dyn;                 // 64*128
    float* sAT   = dyn + 8192;          // 64*36
    float* sred  = dyn + 8192 + 2304;   // 8*128
    float* sqred = sred + 1024;
    const int tid = threadIdx.x;
    const int r0  = blockIdx.x * 32;

    for (int i = tid; i < 2048; i += 256)
        ((float4*)sW)[i] = ((const float4*)fw1)[i];
    for (int i = tid; i < 32*64; i += 256) {
        const int r = i >> 6, c = i & 63;
        sAT[c*36 + r] = g_feat1[(size_t)(r0 + r) * INF + c];
    }
    __syncthreads();

    const int cg = tid & 31;
    const int rg = tid >> 5;
    const float4 fb = reinterpret_cast<const float4*>(fb1)[cg];
    u64 accp[4][2];
#pragma unroll
    for (int i = 0; i < 4; i++) { accp[i][0] = pk(fb.x, fb.y); accp[i][1] = pk(fb.z, fb.w); }

    const ulonglong2* sWq = (const ulonglong2*)sW;
#pragma unroll 4
    for (int kk = 0; kk < 64; kk++) {
        const float4 a = *reinterpret_cast<const float4*>(&sAT[kk*36 + 4*rg]);
        const ulonglong2 ww = sWq[kk*32 + cg];
        const float av[4] = {a.x, a.y, a.z, a.w};
#pragma unroll
        for (int i = 0; i < 4; i++) {
            const u64 aa = pk2(av[i]);
            accp[i][0] = fma2(aa, ww.x, accp[i][0]);
            accp[i][1] = fma2(aa, ww.y, accp[i][1]);
        }
    }
    float s[4] = {0,0,0,0}, sq[4] = {0,0,0,0};
#pragma unroll
    for (int i = 0; i < 4; i++) {
        const float2 lo = upk(accp[i][0]), hi = upk(accp[i][1]);
        float4 o = make_float4(lo.x, lo.y, hi.x, hi.y);
        *reinterpret_cast<float4*>(&g_lin1[(size_t)(r0 + 4*rg + i) * OUTF + 4*cg]) = o;
        s[0] += o.x; s[1] += o.y; s[2] += o.z; s[3] += o.w;
        sq[0] = fmaf(o.x,o.x,sq[0]); sq[1] = fmaf(o.y,o.y,sq[1]);
        sq[2] = fmaf(o.z,o.z,sq[2]); sq[3] = fmaf(o.w,o.w,sq[3]);
    }
#pragma unroll
    for (int qq = 0; qq < 4; qq++) { sred[rg*128 + 4*cg + qq] = s[qq]; sqred[rg*128 + 4*cg + qq] = sq[qq]; }
    __syncthreads();
    if (tid < 128) {
        float a = 0.f, v = 0.f;
#pragma unroll
        for (int r = 0; r < 8; r++) { a += sred[r*128 + tid]; v += sqred[r*128 + tid]; }
        g_part[blockIdx.x*256 + tid]       = a;
        g_part[blockIdx.x*256 + 128 + tid] = v;
    }
}

// ==== K4: GEMM2 with BN1+relu on load, [16384,128]@[128,128]+fb2, stats =====
__global__ __launch_bounds__(256) void gemm2_kernel(
    const float* __restrict__ fw2, const float* __restrict__ fb2) {
    extern __shared__ float dyn[];
    float* sW    = dyn;                  // 128*128
    float* sAT   = dyn + 16384;          // 128*36
    float* sred  = dyn + 16384 + 4608;   // 8*128
    float* sqred = sred + 1024;
    const int tid = threadIdx.x;
    const int r0  = blockIdx.x * 32;

    for (int i = tid; i < 4096; i += 256)
        ((float4*)sW)[i] = ((const float4*)fw2)[i];
    const float* bn = g_bn;       // stage 0
    for (int i = tid; i < 32*128; i += 256) {
        const int r = i >> 7, c = i & 127;
        float v = g_lin1[(size_t)(r0 + r) * OUTF + c];
        v = fmaf(v, bn[c], bn[128 + c]);
        sAT[c*36 + r] = fmaxf(v, 0.f);
    }
    __syncthreads();

    const int cg = tid & 31;
    const int rg = tid >> 5;
    const float4 fb = reinterpret_cast<const float4*>(fb2)[cg];
    u64 accp[4][2];
#pragma unroll
    for (int i = 0; i < 4; i++) { accp[i][0] = pk(fb.x, fb.y); accp[i][1] = pk(fb.z, fb.w); }

    const ulonglong2* sWq = (const ulonglong2*)sW;
#pragma unroll 4
    for (int kk = 0; kk < 128; kk++) {
        const float4 a = *reinterpret_cast<const float4*>(&sAT[kk*36 + 4*rg]);
        const ulonglong2 ww = sWq[kk*32 + cg];
        const float av[4] = {a.x, a.y, a.z, a.w};
#pragma unroll
        for (int i = 0; i < 4; i++) {
            const u64 aa = pk2(av[i]);
            accp[i][0] = fma2(aa, ww.x, accp[i][0]);
            accp[i][1] = fma2(aa, ww.y, accp[i][1]);
        }
    }
    float s[4] = {0,0,0,0}, sq[4] = {0,0,0,0};
#pragma unroll
    for (int i = 0; i < 4; i++) {
        const float2 lo = upk(accp[i][0]), hi = upk(accp[i][1]);
        float4 o = make_float4(lo.x, lo.y, hi.x, hi.y);
        *reinterpret_cast<float4*>(&g_lin2[(size_t)(r0 + 4*rg + i) * OUTF + 4*cg]) = o;
        s[0] += o.x; s[1] += o.y; s[2] += o.z; s[3] += o.w;
        sq[0] = fmaf(o.x,o.x,sq[0]); sq[1] = fmaf(o.y,o.y,sq[1]);
        sq[2] = fmaf(o.z,o.z,sq[2]); sq[3] = fmaf(o.w,o.w,sq[3]);
    }
#pragma unroll
    for (int qq = 0; qq < 4; qq++) { sred[rg*128 + 4*cg + qq] = s[qq]; sqred[rg*128 + 4*cg + qq] = sq[qq]; }
    __syncthreads();
    if (tid < 128) {
        float a = 0.f, v = 0.f;
#pragma unroll
        for (int r = 0; r < 8; r++) { a += sred[r*128 + tid]; v += sqred[r*128 + tid]; }
        g_part[512*256 + blockIdx.x*256 + tid]       = a;
        g_part[512*256 + blockIdx.x*256 + 128 + tid] = v;
    }
}

// ======== finalize BN coefficients (parallelized: 1024 threads) =============
__global__ __launch_bounds__(1024) void finstats_kernel(
    int sel, const float* __restrict__ gamma, const float* __restrict__ beta) {
    __shared__ float red[4*256];
    __shared__ float tot[256];
    const float* part = g_part + sel * (512*256);
    float* bn = g_bn + sel * (2*OUTF);
    const int t = threadIdx.x;
    const int c = t & 255;
    const int g = t >> 8;
    float s = 0.f;
    const int rbeg = g * 128;
#pragma unroll 4
    for (int i = 0; i < 128; i++) s += part[(rbeg + i)*256 + c];
    red[g*256 + c] = s;
    __syncthreads();
    if (t < 256) tot[t] = (red[t] + red[256 + t]) + (red[512 + t] + red[768 + t]);
    __syncthreads();
    if (t < 128) {
        const float inv_n = 1.f / (float)NROW;
        const float m  = tot[t] * inv_n;
        const float v  = tot[128 + t] * inv_n - m * m;
        const float rs = rsqrtf(v + 1e-5f);
        const float a  = rs * gamma[t];
        bn[t]       = a;
        bn[128 + t] = beta[t] - m * a;
    }
}

// ===================== K7: final BN2 -> output (vectorized) =================
__global__ __launch_bounds__(1024) void final_kernel(float* __restrict__ out) {
    const int i = blockIdx.x * 1024 + threadIdx.x;   // float4 units
    const int c0 = (i << 2) & 127;
    const float* bn = g_bn + 2*OUTF;
    const float4 v = ((const float4*)g_lin2)[i];
    float4 o;
    o.x = fmaf(v.x, bn[c0],   bn[128 + c0]);
    o.y = fmaf(v.y, bn[c0+1], bn[128 + c0 + 1]);
    o.z = fmaf(v.z, bn[c0+2], bn[128 + c0 + 2]);
    o.w = fmaf(v.w, bn[c0+3], bn[128 + c0 + 3]);
    ((float4*)out)[i] = o;
}

// ============================================================================
extern "C" void kernel_launch(void* const* d_in, const int* in_sizes, int n_in,
                              void* d_out, int out_size) {
    (void)in_sizes; (void)n_in; (void)out_size;
    const float* x   = (const float*)d_in[0];
    const float* pos = (const float*)d_in[1];
    const float* rw1 = (const float*)d_in[2];
    const float* rb1 = (const float*)d_in[3];
    const float* rw2 = (const float*)d_in[4];
    const float* rb2 = (const float*)d_in[5];
    const float* rw3 = (const float*)d_in[6];
    const float* rb3 = (const float*)d_in[7];
    const float* fw1 = (const float*)d_in[8];
    const float* fb1 = (const float*)d_in[9];
    const float* g1  = (const float*)d_in[10];
    const float* b1  = (const float*)d_in[11];
    const float* fw2 = (const float*)d_in[12];
    const float* fb2 = (const float*)d_in[13];
    const float* g2  = (const float*)d_in[14];
    const float* b2  = (const float*)d_in[15];
    float* out = (float*)d_out;

    // stage MLP weights into constant memory (D2D async copies; capturable)
    cudaMemcpyToSymbolAsync(cw1, rw1, 10*32*4,  0, cudaMemcpyDeviceToDevice);
    cudaMemcpyToSymbolAsync(cb1, rb1, 32*4,     0, cudaMemcpyDeviceToDevice);
    cudaMemcpyToSymbolAsync(cw2, rw2, 32*64*4,  0, cudaMemcpyDeviceToDevice);
    cudaMemcpyToSymbolAsync(cb2, rb2, 64*4,     0, cudaMemcpyDeviceToDevice);
    cudaMemcpyToSymbolAsync(cw3, rw3, 64*64*4,  0, cudaMemcpyDeviceToDevice);
    cudaMemcpyToSymbolAsync(cb3, rb3, 64*4,     0, cudaMemcpyDeviceToDevice);

    // 2 nops so the ncu capture (4th kernel) lands on relconv_kernel.
    nop_kernel<<<1, 32>>>();
    nop_kernel<<<1, 32>>>();

    const int smem_knn = (NPTS*3 + 2048 + 16 + 512 + 512 + 16 + 4) * 4;  // ~60.4 KB
    cudaFuncSetAttribute(knn_kernel, cudaFuncAttributeMaxDynamicSharedMemorySize, smem_knn);
    knn_kernel<<<1024, 512, smem_knn>>>(pos);

    relconv_kernel<<<HALFITEM/128, 128>>>(x, pos);

    const int smem1 = (8192 + 2304 + 2048) * 4;
    cudaFuncSetAttribute(gemm1_kernel, cudaFuncAttributeMaxDynamicSharedMemorySize, smem1);
    gemm1_kernel<<<NROW/32, 256, smem1>>>(fw1, fb1);
    finstats_kernel<<<1, 1024>>>(0, g1, b1);

    const int smem2 = (16384 + 4608 + 2048) * 4;
    cudaFuncSetAttribute(gemm2_kernel, cudaFuncAttributeMaxDynamicSharedMemorySize, smem2);
    gemm2_kernel<<<NROW/32, 256, smem2>>>(fw2, fb2);
    finstats_kernel<<<1, 1024>>>(1, g2, b2);

    final_kernel<<<524288/1024, 1024>>>(out);
}